// round 14
// baseline (speedup 1.0000x reference)
#include <cuda_runtime.h>
#include <math.h>
#include <stdint.h>

#define S 2048
#define D 768
#define H 12
#define HD 64
#define FF 3072
#define L 6
#define PAD_IDX 1
#define WIN 128
#define BQ 16
#define KWP 320            // padded window columns (5 chunks of 64); valid keys are first 272
#define APAD 132           // As row pad: 132*4=528B (16B-aligned), 2-way STS conflict only

// ---------------- scratch (static device globals: no allocation) ----------------
__device__ float g_x[S*D];
__device__ float g_q[S*D];
__device__ float g_k[S*D];
__device__ float g_v[S*D];
__device__ float g_o[S*D];
__device__ float g_t[S*D];
__device__ float g_f[S*FF];
__device__ int   g_pos[S];
__device__ float g_brel[H*257];   // bias per (head, rp+128), rp in [-128,128]

template<int ID>
__device__ __forceinline__ float* buf() {
    if constexpr (ID == 0) return g_x;
    else if constexpr (ID == 4) return g_o;
    else if constexpr (ID == 5) return g_t;
    else return g_f;   // ID == 6
}

// packed f32x2 helpers (sm_100+ baseline PTX; FFMA2 path)
__device__ __forceinline__ unsigned long long dup_f32(float a) {
    unsigned long long r;
    asm("mov.b64 %0, {%1, %1};" : "=l"(r) : "f"(a));
    return r;
}
#define FMA2(acc, a2, b2) \
    asm("fma.rn.f32x2 %0, %1, %2, %0;" : "+l"(acc) : "l"(a2), "l"(b2))

// ---------------- positions (fairseq make_positions) ----------------
__global__ void pos_kernel(const int* __restrict__ tokens) {
    __shared__ int s_sum[256];
    int tid = threadIdx.x;
    int base = tid * 8;
    int np[8]; int tot = 0;
#pragma unroll
    for (int i = 0; i < 8; i++) { np[i] = (tokens[base+i] != PAD_IDX) ? 1 : 0; tot += np[i]; }
    s_sum[tid] = tot;
    __syncthreads();
    if (tid == 0) {
        int run = 0;
        for (int i = 0; i < 256; i++) { int v = s_sum[i]; s_sum[i] = run; run += v; }
    }
    __syncthreads();
    int run = s_sum[tid];
#pragma unroll
    for (int i = 0; i < 8; i++) {
        run += np[i];
        g_pos[base+i] = np[i] ? (PAD_IDX + run) : PAD_IDX;
    }
}

// ---------------- relative position bias table ----------------
__global__ void relbias_kernel(const float* __restrict__ rel_bias) {
    int j = threadIdx.x;
    if (j >= 257) return;
    int rp = j - 128;
    int n = -rp;
    int ret = (n < 0) ? 16 : 0;
    n = abs(n);
    int val;
    if (n < 8) val = n;
    else {
        val = 8 + (int)(logf((float)n / 8.0f) / logf(16.0f) * 8.0f);
        if (val > 15) val = 15;
    }
    int bucket = ret + val;
    for (int h = 0; h < H; h++)
        g_brel[h*257 + j] = rel_bias[bucket*H + h];
}

// ---------------- embedding ----------------
__global__ void embed_kernel(const int* __restrict__ tokens, const int* __restrict__ segs,
                             const float* __restrict__ emb, const float* __restrict__ pemb,
                             const float* __restrict__ semb) {
    int s = blockIdx.x;
    int c = threadIdx.x * 4;
    int tok = tokens[s];
    float4* dst = (float4*)&g_x[(size_t)s*D + c];
    if (tok == PAD_IDX) { *dst = make_float4(0.f,0.f,0.f,0.f); return; }
    float4 a = *(const float4*)&emb[(size_t)tok*D + c];
    float4 p = *(const float4*)&pemb[(size_t)g_pos[s]*D + c];
    float4 g = *(const float4*)&semb[(size_t)segs[s]*D + c];
    *dst = make_float4(a.x+p.x+g.x, a.y+p.y+g.y, a.z+p.z+g.z, a.w+p.w+g.w);
}

// ---------------- SGEMM core: C[M,N] = alpha*(A[M,K]@B[K,N] + bias), M=2048 ----------------
// BM=128, BN=64, BK=16, 256 threads, 4x8 per-thread tile.
// Double-buffered smem + register prefetch; packed fma.rn.f32x2 inner loop.
__device__ __forceinline__ void gemm_core(
    const float* __restrict__ A, const float* __restrict__ Bm,
    const float* __restrict__ bias, float* __restrict__ C,
    int N, int K, float alpha, int relu)
{
    __shared__ float As[2][16][APAD];
    __shared__ float Bs[2][16][64];
    int tid = threadIdx.x;          // 0..255
    int m0 = blockIdx.y * 128;
    int n0 = blockIdx.x * 64;
    int tx = tid & 7;               // n-group 0..7
    int ty = tid >> 3;              // m-group 0..31

    unsigned long long acc2[4][4];
#pragma unroll
    for (int i = 0; i < 4; i++)
#pragma unroll
        for (int j = 0; j < 4; j++) acc2[i][j] = 0ull;

    int tA_r = tid >> 2;            // 0..63 (two rows: +0, +64)
    int tA_c = (tid & 3) << 2;      // 0,4,8,12
    int tB_r = tid >> 4;            // 0..15
    int tB_c = (tid & 15) << 2;

    float4 pa[2]; float4 pb;

    // ---- prologue: tile 0 ----
    pa[0] = *(const float4*)(A + (size_t)(m0 + tA_r     )*K + tA_c);
    pa[1] = *(const float4*)(A + (size_t)(m0 + tA_r + 64)*K + tA_c);
    pb    = *(const float4*)(Bm + (size_t)tB_r*N + n0 + tB_c);
#pragma unroll
    for (int i = 0; i < 2; i++) {
        int row = tA_r + (i << 6);
        As[0][tA_c+0][row] = pa[i].x; As[0][tA_c+1][row] = pa[i].y;
        As[0][tA_c+2][row] = pa[i].z; As[0][tA_c+3][row] = pa[i].w;
    }
    *(float4*)&Bs[0][tB_r][tB_c] = pb;
    __syncthreads();

    const int NT = K >> 4;
    for (int t = 0; t < NT; t++) {
        int cur = t & 1;
        bool pf = (t + 1 < NT);
        int kt = (t + 1) << 4;
        if (pf) {
            pa[0] = *(const float4*)(A + (size_t)(m0 + tA_r     )*K + kt + tA_c);
            pa[1] = *(const float4*)(A + (size_t)(m0 + tA_r + 64)*K + kt + tA_c);
            pb    = *(const float4*)(Bm + (size_t)(kt + tB_r)*N + n0 + tB_c);
        }
#pragma unroll
        for (int k = 0; k < 16; k++) {
            float4 a4 = *(float4*)&As[cur][k][ty*4];
            unsigned long long b2[4];
            {
                ulonglong2 t0 = *(ulonglong2*)&Bs[cur][k][tx*8];
                ulonglong2 t1 = *(ulonglong2*)&Bs[cur][k][tx*8+4];
                b2[0] = t0.x; b2[1] = t0.y; b2[2] = t1.x; b2[3] = t1.y;
            }
            float av[4] = {a4.x, a4.y, a4.z, a4.w};
#pragma unroll
            for (int i = 0; i < 4; i++) {
                unsigned long long ad = dup_f32(av[i]);
                FMA2(acc2[i][0], ad, b2[0]);
                FMA2(acc2[i][1], ad, b2[1]);
                FMA2(acc2[i][2], ad, b2[2]);
                FMA2(acc2[i][3], ad, b2[3]);
            }
        }
        if (pf) {
            int nxt = cur ^ 1;
#pragma unroll
            for (int i = 0; i < 2; i++) {
                int row = tA_r + (i << 6);
                As[nxt][tA_c+0][row] = pa[i].x; As[nxt][tA_c+1][row] = pa[i].y;
                As[nxt][tA_c+2][row] = pa[i].z; As[nxt][tA_c+3][row] = pa[i].w;
            }
            *(float4*)&Bs[nxt][tB_r][tB_c] = pb;
        }
        __syncthreads();
    }

    float bv[8];
#pragma unroll
    for (int j = 0; j < 8; j++) bv[j] = bias[n0 + tx*8 + j];
#pragma unroll
    for (int i = 0; i < 4; i++) {
        int row = m0 + ty*4 + i;
        float out[8];
#pragma unroll
        for (int j = 0; j < 4; j++) {
            float2 p = *(float2*)&acc2[i][j];
            float v0 = (p.x + bv[2*j  ]) * alpha;
            float v1 = (p.y + bv[2*j+1]) * alpha;
            if (relu) { v0 = fmaxf(v0, 0.f); v1 = fmaxf(v1, 0.f); }
            out[2*j] = v0; out[2*j+1] = v1;
        }
        *(float4*)(C + (size_t)row*N + n0 + tx*8)     = *(float4*)&out[0];
        *(float4*)(C + (size_t)row*N + n0 + tx*8 + 4) = *(float4*)&out[4];
    }
}

template<int AID, int CID>
__global__ __launch_bounds__(256) void gemm_tpl(const float* __restrict__ Bm,
    const float* __restrict__ bias, int N, int K, float alpha, int relu)
{
    gemm_core(buf<AID>(), Bm, bias, buf<CID>(), N, K, alpha, relu);
}

__global__ __launch_bounds__(256) void gemm_qkv(
    const float* __restrict__ Wq, const float* __restrict__ Wk, const float* __restrict__ Wv,
    const float* __restrict__ bq, const float* __restrict__ bk, const float* __restrict__ bv)
{
    const float* Bm; const float* bias; float* C; float alpha = 1.f;
    if (blockIdx.z == 0)      { Bm = Wq; bias = bq; C = g_q; alpha = 0.125f; } // 1/sqrt(64)
    else if (blockIdx.z == 1) { Bm = Wk; bias = bk; C = g_k; }
    else                      { Bm = Wv; bias = bv; C = g_v; }
    gemm_core(g_x, Bm, bias, C, D, D, alpha, 0);
}

// ---------------- fused windowed attention (R12 verbatim) ----------------
__global__ __launch_bounds__(256) void attn_kernel(const int* __restrict__ tokens) {
    __shared__ float Qs[BQ][HD];
    __shared__ float KV[64][68];
    __shared__ float Sc[BQ][KWP];
    int h   = blockIdx.y;
    int q0  = blockIdx.x * BQ;
    int tid = threadIdx.x;
    int kstart = q0 - WIN;

    { int i = tid >> 4, c = (tid & 15) << 2;
      *(float4*)&Qs[i][c] = *(const float4*)(g_q + (size_t)(q0+i)*D + h*HD + c); }

    int jj = tid & 63;
    int i0 = (tid >> 6) << 2;

    for (int c0 = 0; c0 < KWP; c0 += 64) {
        int kb = kstart + c0;
        if (kb >= S || kb + 63 < 0) {
#pragma unroll
            for (int r = 0; r < 4; r++) Sc[i0+r][c0+jj] = -3.0e38f;
            continue;
        }
        __syncthreads();
        for (int e = tid; e < 1024; e += 256) {
            int r = e >> 4, d4 = (e & 15) << 2;
            int key = kb + r;
            float4 kv = (key >= 0 && key < S) ? *(const float4*)(g_k + (size_t)key*D + h*HD + d4)
                                              : make_float4(0.f,0.f,0.f,0.f);
            *(float4*)&KV[r][d4] = kv;
        }
        __syncthreads();
        float a0=0.f, a1=0.f, a2=0.f, a3=0.f;
#pragma unroll
        for (int dd = 0; dd < 64; dd += 4) {
            float4 kv = *(float4*)&KV[jj][dd];
            float4 v0 = *(float4*)&Qs[i0+0][dd];
            float4 v1 = *(float4*)&Qs[i0+1][dd];
            float4 v2 = *(float4*)&Qs[i0+2][dd];
            float4 v3 = *(float4*)&Qs[i0+3][dd];
            a0 = fmaf(v0.x,kv.x, fmaf(v0.y,kv.y, fmaf(v0.z,kv.z, fmaf(v0.w,kv.w, a0))));
            a1 = fmaf(v1.x,kv.x, fmaf(v1.y,kv.y, fmaf(v1.z,kv.z, fmaf(v1.w,kv.w, a1))));
            a2 = fmaf(v2.x,kv.x, fmaf(v2.y,kv.y, fmaf(v2.z,kv.z, fmaf(v2.w,kv.w, a2))));
            a3 = fmaf(v3.x,kv.x, fmaf(v3.y,kv.y, fmaf(v3.z,kv.z, fmaf(v3.w,kv.w, a3))));
        }
        int key = kb + jj;
        bool inr = (key >= 0 && key < S);
        float padp = (inr && tokens[key] == PAD_IDX) ? -1e30f : 0.f;
        float av[4] = {a0, a1, a2, a3};
#pragma unroll
        for (int r = 0; r < 4; r++) {
            int rp = key - (q0 + i0 + r);
            float sc;
            if (!inr || rp < -WIN || rp > WIN) sc = -3.0e38f;
            else sc = av[r] + g_brel[h*257 + rp + WIN] + padp;
            Sc[i0+r][c0+jj] = sc;
        }
    }
    __syncthreads();

    {
        int warp = tid >> 5, lane = tid & 31;
#pragma unroll
        for (int rr = 0; rr < 2; rr++) {
            int i = warp*2 + rr;
            float m = -3.4e38f;
            for (int j = lane; j < KWP; j += 32) m = fmaxf(m, Sc[i][j]);
#pragma unroll
            for (int off = 16; off; off >>= 1) m = fmaxf(m, __shfl_xor_sync(0xffffffffu, m, off));
            float ssum = 0.f;
            for (int j = lane; j < KWP; j += 32) {
                float e = expf(Sc[i][j] - m);
                Sc[i][j] = e; ssum += e;
            }
#pragma unroll
            for (int off = 16; off; off >>= 1) ssum += __shfl_xor_sync(0xffffffffu, ssum, off);
            float inv = 1.f / ssum;
            for (int j = lane; j < KWP; j += 32) Sc[i][j] *= inv;
        }
    }
    __syncthreads();

    int dd = tid & 63;
    float o0=0.f, o1=0.f, o2=0.f, o3=0.f;
    for (int c0 = 0; c0 < KWP; c0 += 64) {
        int kb = kstart + c0;
        if (kb >= S || kb + 63 < 0) continue;
        __syncthreads();
        {
            int r0 = (tid >> 4) << 2, d0 = (tid & 15) << 2;
#pragma unroll
            for (int u = 0; u < 4; u++) {
                int key = kb + r0 + u;
                float4 v = (key >= 0 && key < S) ? *(const float4*)(g_v + (size_t)key*D + h*HD + d0)
                                                 : make_float4(0.f,0.f,0.f,0.f);
                KV[d0+0][r0+u] = v.x; KV[d0+1][r0+u] = v.y;
                KV[d0+2][r0+u] = v.z; KV[d0+3][r0+u] = v.w;
            }
        }
        __syncthreads();
#pragma unroll
        for (int j = 0; j < 64; j += 4) {
            float4 vv = *(float4*)&KV[dd][j];
            float4 s0 = *(float4*)&Sc[i0+0][c0+j];
            float4 s1 = *(float4*)&Sc[i0+1][c0+j];
            float4 s2 = *(float4*)&Sc[i0+2][c0+j];
            float4 s3 = *(float4*)&Sc[i0+3][c0+j];
            o0 = fmaf(s0.x,vv.x, fmaf(s0.y,vv.y, fmaf(s0.z,vv.z, fmaf(s0.w,vv.w, o0))));
            o1 = fmaf(s1.x,vv.x, fmaf(s1.y,vv.y, fmaf(s1.z,vv.z, fmaf(s1.w,vv.w, o1))));
            o2 = fmaf(s2.x,vv.x, fmaf(s2.y,vv.y, fmaf(s2.z,vv.z, fmaf(s2.w,vv.w, o2))));
            o3 = fmaf(s3.x,vv.x, fmaf(s3.y,vv.y, fmaf(s3.z,vv.z, fmaf(s3.w,vv.w, o3))));
        }
    }
    g_o[(size_t)(q0+i0+0)*D + h*HD + dd] = o0;
    g_o[(size_t)(q0+i0+1)*D + h*HD + dd] = o1;
    g_o[(size_t)(q0+i0+2)*D + h*HD + dd] = o2;
    g_o[(size_t)(q0+i0+3)*D + h*HD + dd] = o3;
}

// ---------------- residual + LayerNorm (R12 verbatim) ----------------
template<bool TO_OUT>
__global__ __launch_bounds__(256) void ln_kernel(const float* __restrict__ sc,
    const float* __restrict__ bb, float* __restrict__ outp)
{
    float* dst = TO_OUT ? outp : g_x;
    __shared__ float red[256];
    __shared__ float sh_m, sh_r;
    int row = blockIdx.x, tid = threadIdx.x;
    size_t base = (size_t)row * D;
    float v0 = g_x[base + tid      ] + g_t[base + tid      ];
    float v1 = g_x[base + tid + 256] + g_t[base + tid + 256];
    float v2 = g_x[base + tid + 512] + g_t[base + tid + 512];
    red[tid] = v0 + v1 + v2;
    __syncthreads();
#pragma unroll
    for (int o2 = 128; o2; o2 >>= 1) { if (tid < o2) red[tid] += red[tid + o2]; __syncthreads(); }
    if (tid == 0) sh_m = red[0] * (1.f / 768.f);
    __syncthreads();
    float m = sh_m;
    float d0 = v0 - m, d1 = v1 - m, d2 = v2 - m;
    red[tid] = d0*d0 + d1*d1 + d2*d2;
    __syncthreads();
#pragma unroll
    for (int o2 = 128; o2; o2 >>= 1) { if (tid < o2) red[tid] += red[tid + o2]; __syncthreads(); }
    if (tid == 0) sh_r = rsqrtf(red[0] * (1.f / 768.f) + 1e-5f);
    __syncthreads();
    float r = sh_r;
    dst[base + tid      ] = d0 * r * sc[tid      ] + bb[tid      ];
    dst[base + tid + 256] = d1 * r * sc[tid + 256] + bb[tid + 256];
    dst[base + tid + 512] = d2 * r * sc[tid + 512] + bb[tid + 512];
}

// ---------------- driver ----------------
extern "C" void kernel_launch(void* const* d_in, const int* in_sizes, int n_in,
                              void* d_out, int out_size)
{
    const int*   tokens = (const int*)  d_in[0];
    const int*   segs   = (const int*)  d_in[1];
    const float* emb    = (const float*)d_in[2];
    const float* pemb   = (const float*)d_in[3];
    const float* semb   = (const float*)d_in[4];
    const float* relb   = (const float*)d_in[5];
    const float* Wq     = (const float*)d_in[6];
    const float* bq     = (const float*)d_in[7];
    const float* Wk     = (const float*)d_in[8];
    const float* bk     = (const float*)d_in[9];
    const float* Wv     = (const float*)d_in[10];
    const float* bv     = (const float*)d_in[11];
    const float* Wo     = (const float*)d_in[12];
    const float* bo     = (const float*)d_in[13];
    const float* ln1s   = (const float*)d_in[14];
    const float* ln1b   = (const float*)d_in[15];
    const float* W1     = (const float*)d_in[16];
    const float* b1     = (const float*)d_in[17];
    const float* W2     = (const float*)d_in[18];
    const float* b2     = (const float*)d_in[19];
    const float* ln2s   = (const float*)d_in[20];
    const float* ln2b   = (const float*)d_in[21];
    float* out = (float*)d_out;

    dim3 g768(D/64, S/128);        // (12, 16)
    dim3 gFF(FF/64, S/128);        // (48, 16)
    dim3 gqkv(D/64, S/128, 3);     // (12, 16, 3)
    dim3 gattn(S/BQ, H);           // (128, 12)

    pos_kernel<<<1, 256>>>(tokens);
    relbias_kernel<<<1, 288>>>(relb);
    embed_kernel<<<S, 192>>>(tokens, segs, emb, pemb, semb);

    for (int l = 0; l < L; l++) {
        size_t wdd = (size_t)l * D * D;
        gemm_qkv<<<gqkv, 256>>>(Wq + wdd, Wk + wdd, Wv + wdd,
                                bq + l*D, bk + l*D, bv + l*D);
        attn_kernel<<<gattn, 256>>>(tokens);
        gemm_tpl<4,5><<<g768, 256>>>(Wo + wdd, bo + l*D, D, D, 1.f, 0);
        ln_kernel<false><<<S, 256>>>(ln1s + l*D, ln1b + l*D, nullptr);
        gemm_tpl<0,6><<<gFF, 256>>>(W1 + (size_t)l*D*FF, b1 + (size_t)l*FF, FF, D, 1.f, 1);
        gemm_tpl<6,5><<<g768, 256>>>(W2 + (size_t)l*FF*D, b2 + l*D, D, FF, 1.f, 0);
        if (l == L-1) ln_kernel<true ><<<S, 256>>>(ln2s + l*D, ln2b + l*D, out);
        else          ln_kernel<false><<<S, 256>>>(ln2s + l*D, ln2b + l*D, nullptr);
    }
}

// round 16
// speedup vs baseline: 1.4782x; 1.4782x over previous
#include <cuda_runtime.h>
#include <math.h>
#include <stdint.h>

#define S 2048
#define D 768
#define H 12
#define HD 64
#define FF 3072
#define L 6
#define PAD_IDX 1
#define WIN 128
#define BQ 16
#define KWP 320            // padded window columns (5 chunks of 64); valid keys are first 272

// ---------------- scratch (static device globals: no allocation) ----------------
// RULE: these are referenced ONLY from device code (never passed as kernel args from host).
__device__ float g_x[S*D];
__device__ float g_q[S*D];
__device__ float g_k[S*D];
__device__ float g_v[S*D];
__device__ float g_o[S*D];
__device__ float g_t[S*D];
__device__ float g_f[S*FF];
__device__ float g_xt[D*S];      // transposed activations [K][M=2048]
__device__ float g_ot[D*S];
__device__ float g_ft[FF*S];
__device__ int   g_pos[S];
__device__ float g_brel[H*257];  // bias per (head, rp+128), rp in [-128,128]

template<int ID>
__device__ __forceinline__ float* tbuf() {
    if constexpr (ID == 0) return g_xt;
    else if constexpr (ID == 4) return g_ot;
    else return g_ft;   // 6
}
template<int ID>
__device__ __forceinline__ float* buf() {
    if constexpr (ID == 5) return g_t;
    else return g_f;    // 6
}

// packed f32x2 helpers (sm_100+ baseline PTX; FFMA2 path)
__device__ __forceinline__ unsigned long long dup_f32(float a) {
    unsigned long long r;
    asm("mov.b64 %0, {%1, %1};" : "=l"(r) : "f"(a));
    return r;
}
#define FMA2(acc, a2, b2) \
    asm("fma.rn.f32x2 %0, %1, %2, %0;" : "+l"(acc) : "l"(a2), "l"(b2))

// ---------------- positions (fairseq make_positions) ----------------
__global__ void pos_kernel(const int* __restrict__ tokens) {
    __shared__ int s_sum[256];
    int tid = threadIdx.x;
    int base = tid * 8;
    int np[8]; int tot = 0;
#pragma unroll
    for (int i = 0; i < 8; i++) { np[i] = (tokens[base+i] != PAD_IDX) ? 1 : 0; tot += np[i]; }
    s_sum[tid] = tot;
    __syncthreads();
    if (tid == 0) {
        int run = 0;
        for (int i = 0; i < 256; i++) { int v = s_sum[i]; s_sum[i] = run; run += v; }
    }
    __syncthreads();
    int run = s_sum[tid];
#pragma unroll
    for (int i = 0; i < 8; i++) {
        run += np[i];
        g_pos[base+i] = np[i] ? (PAD_IDX + run) : PAD_IDX;
    }
}

// ---------------- relative position bias table ----------------
__global__ void relbias_kernel(const float* __restrict__ rel_bias) {
    int j = threadIdx.x;
    if (j >= 257) return;
    int rp = j - 128;
    int n = -rp;
    int ret = (n < 0) ? 16 : 0;
    n = abs(n);
    int val;
    if (n < 8) val = n;
    else {
        val = 8 + (int)(logf((float)n / 8.0f) / logf(16.0f) * 8.0f);
        if (val > 15) val = 15;
    }
    int bucket = ret + val;
    for (int h = 0; h < H; h++)
        g_brel[h*257 + j] = rel_bias[bucket*H + h];
}

// ---------------- embedding ----------------
__global__ void embed_kernel(const int* __restrict__ tokens, const int* __restrict__ segs,
                             const float* __restrict__ emb, const float* __restrict__ pemb,
                             const float* __restrict__ semb) {
    int s = blockIdx.x;
    int c = threadIdx.x * 4;
    int tok = tokens[s];
    float4* dst = (float4*)&g_x[(size_t)s*D + c];
    if (tok == PAD_IDX) { *dst = make_float4(0.f,0.f,0.f,0.f); return; }
    float4 a = *(const float4*)&emb[(size_t)tok*D + c];
    float4 p = *(const float4*)&pemb[(size_t)g_pos[s]*D + c];
    float4 g = *(const float4*)&semb[(size_t)segs[s]*D + c];
    *dst = make_float4(a.x+p.x+g.x, a.y+p.y+g.y, a.z+p.z+g.z, a.w+p.w+g.w);
}

// ---------------- activation transpose (symbol-based): src[RR][CC] -> dst[CC][RR] ----------------
// ID 0: g_x -> g_xt (RR=S, CC=D); ID 4: g_o -> g_ot; ID 6: g_f -> g_ft (CC=FF)
template<int ID>
__global__ void transp_tpl(int RR, int CC) {
    const float* src;
    float* dst;
    if constexpr (ID == 0)      { src = g_x; dst = g_xt; }
    else if constexpr (ID == 4) { src = g_o; dst = g_ot; }
    else                        { src = g_f; dst = g_ft; }
    __shared__ float t[32][33];
    int c0 = blockIdx.x*32, r0 = blockIdx.y*32;
    int tx = threadIdx.x, ty = threadIdx.y;   // 32 x 8
#pragma unroll
    for (int i = 0; i < 4; i++)
        t[ty + i*8][tx] = src[(size_t)(r0 + ty + i*8)*CC + c0 + tx];
    __syncthreads();
#pragma unroll
    for (int i = 0; i < 4; i++)
        dst[(size_t)(c0 + ty + i*8)*RR + r0 + tx] = t[tx][ty + i*8];
}

// ---------------- SGEMM core: C[M,N] = alpha*(At^T@B + bias), M=2048 ----------------
// At: [K][S] pre-transposed activations. BM=128, BN=64, BK=16, 128 threads, 8x8 tile.
// Double-buffered smem, register prefetch, packed fma.rn.f32x2.
// A smem fill is a straight float4 copy (no scatter, no conflicts).
__device__ __forceinline__ void gemm_core(
    const float* __restrict__ At, const float* __restrict__ Bm,
    const float* __restrict__ bias, float* __restrict__ C,
    int N, int K, float alpha, int relu)
{
    __shared__ float As[2][16][136];   // 544B rows: 16B-aligned
    __shared__ float Bs[2][16][64];
    int tid = threadIdx.x;
    int m0 = blockIdx.y * 128;
    int n0 = blockIdx.x * 64;
    int tx = tid & 7;
    int ty = tid >> 3;

    unsigned long long acc2[8][4];
#pragma unroll
    for (int i = 0; i < 8; i++)
#pragma unroll
        for (int j = 0; j < 4; j++) acc2[i][j] = 0ull;

    int aK = tid >> 5;             // 0..3; k rows aK, aK+4, aK+8, aK+12
    int aC = (tid & 31) << 2;      // m offset 0..124
    int tB_r0 = tid >> 4;          // 0..7
    int tB_c  = (tid & 15) << 2;

    float4 pa[4]; float4 pb[2];

    // ---- prologue: tile 0 ----
#pragma unroll
    for (int i = 0; i < 4; i++)
        pa[i] = *(const float4*)(At + (size_t)(aK + 4*i)*S + m0 + aC);
    pb[0] = *(const float4*)(Bm + (size_t)(tB_r0    )*N + n0 + tB_c);
    pb[1] = *(const float4*)(Bm + (size_t)(tB_r0 + 8)*N + n0 + tB_c);
#pragma unroll
    for (int i = 0; i < 4; i++)
        *(float4*)&As[0][aK + 4*i][aC] = pa[i];
    *(float4*)&Bs[0][tB_r0    ][tB_c] = pb[0];
    *(float4*)&Bs[0][tB_r0 + 8][tB_c] = pb[1];
    __syncthreads();

    const int NT = K >> 4;
    for (int t = 0; t < NT; t++) {
        int cur = t & 1;
        bool pf = (t + 1 < NT);
        int kt = (t + 1) << 4;
        if (pf) {
#pragma unroll
            for (int i = 0; i < 4; i++)
                pa[i] = *(const float4*)(At + (size_t)(kt + aK + 4*i)*S + m0 + aC);
            pb[0] = *(const float4*)(Bm + (size_t)(kt + tB_r0    )*N + n0 + tB_c);
            pb[1] = *(const float4*)(Bm + (size_t)(kt + tB_r0 + 8)*N + n0 + tB_c);
        }
#pragma unroll
        for (int k = 0; k < 16; k++) {
            float a[8];
            *(float4*)&a[0] = *(float4*)&As[cur][k][ty*8];
            *(float4*)&a[4] = *(float4*)&As[cur][k][ty*8+4];
            unsigned long long b2[4];
            {
                ulonglong2 t0 = *(ulonglong2*)&Bs[cur][k][tx*8];
                ulonglong2 t1 = *(ulonglong2*)&Bs[cur][k][tx*8+4];
                b2[0] = t0.x; b2[1] = t0.y; b2[2] = t1.x; b2[3] = t1.y;
            }
#pragma unroll
            for (int i = 0; i < 8; i++) {
                unsigned long long ad = dup_f32(a[i]);
                FMA2(acc2[i][0], ad, b2[0]);
                FMA2(acc2[i][1], ad, b2[1]);
                FMA2(acc2[i][2], ad, b2[2]);
                FMA2(acc2[i][3], ad, b2[3]);
            }
        }
        if (pf) {
            int nxt = cur ^ 1;
#pragma unroll
            for (int i = 0; i < 4; i++)
                *(float4*)&As[nxt][aK + 4*i][aC] = pa[i];
            *(float4*)&Bs[nxt][tB_r0    ][tB_c] = pb[0];
            *(float4*)&Bs[nxt][tB_r0 + 8][tB_c] = pb[1];
        }
        __syncthreads();
    }

    float bv[8];
#pragma unroll
    for (int j = 0; j < 8; j++) bv[j] = bias[n0 + tx*8 + j];
#pragma unroll
    for (int i = 0; i < 8; i++) {
        int row = m0 + ty*8 + i;
        float out[8];
#pragma unroll
        for (int j = 0; j < 4; j++) {
            float2 p = *(float2*)&acc2[i][j];
            float v0 = (p.x + bv[2*j  ]) * alpha;
            float v1 = (p.y + bv[2*j+1]) * alpha;
            if (relu) { v0 = fmaxf(v0, 0.f); v1 = fmaxf(v1, 0.f); }
            out[2*j] = v0; out[2*j+1] = v1;
        }
        *(float4*)(C + (size_t)row*N + n0 + tx*8)     = *(float4*)&out[0];
        *(float4*)(C + (size_t)row*N + n0 + tx*8 + 4) = *(float4*)&out[4];
    }
}

template<int AID, int CID>
__global__ __launch_bounds__(128) void gemm_tpl(const float* __restrict__ Bm,
    const float* __restrict__ bias, int N, int K, float alpha, int relu)
{
    gemm_core(tbuf<AID>(), Bm, bias, buf<CID>(), N, K, alpha, relu);
}

__global__ __launch_bounds__(128) void gemm_qkv(
    const float* __restrict__ Wq, const float* __restrict__ Wk, const float* __restrict__ Wv,
    const float* __restrict__ bq, const float* __restrict__ bk, const float* __restrict__ bv)
{
    const float* Bm; const float* bias; float* C; float alpha = 1.f;
    if (blockIdx.z == 0)      { Bm = Wq; bias = bq; C = g_q; alpha = 0.125f; } // 1/sqrt(64)
    else if (blockIdx.z == 1) { Bm = Wk; bias = bk; C = g_k; }
    else                      { Bm = Wv; bias = bv; C = g_v; }
    gemm_core(g_xt, Bm, bias, C, D, D, alpha, 0);
}

// ---------------- fused windowed attention (R12 verbatim) ----------------
__global__ __launch_bounds__(256) void attn_kernel(const int* __restrict__ tokens) {
    __shared__ float Qs[BQ][HD];
    __shared__ float KV[64][68];
    __shared__ float Sc[BQ][KWP];
    int h   = blockIdx.y;
    int q0  = blockIdx.x * BQ;
    int tid = threadIdx.x;
    int kstart = q0 - WIN;

    { int i = tid >> 4, c = (tid & 15) << 2;
      *(float4*)&Qs[i][c] = *(const float4*)(g_q + (size_t)(q0+i)*D + h*HD + c); }

    int jj = tid & 63;
    int i0 = (tid >> 6) << 2;

    for (int c0 = 0; c0 < KWP; c0 += 64) {
        int kb = kstart + c0;
        if (kb >= S || kb + 63 < 0) {
#pragma unroll
            for (int r = 0; r < 4; r++) Sc[i0+r][c0+jj] = -3.0e38f;
            continue;
        }
        __syncthreads();
        for (int e = tid; e < 1024; e += 256) {
            int r = e >> 4, d4 = (e & 15) << 2;
            int key = kb + r;
            float4 kv = (key >= 0 && key < S) ? *(const float4*)(g_k + (size_t)key*D + h*HD + d4)
                                              : make_float4(0.f,0.f,0.f,0.f);
            *(float4*)&KV[r][d4] = kv;
        }
        __syncthreads();
        float a0=0.f, a1=0.f, a2=0.f, a3=0.f;
#pragma unroll
        for (int dd = 0; dd < 64; dd += 4) {
            float4 kv = *(float4*)&KV[jj][dd];
            float4 v0 = *(float4*)&Qs[i0+0][dd];
            float4 v1 = *(float4*)&Qs[i0+1][dd];
            float4 v2 = *(float4*)&Qs[i0+2][dd];
            float4 v3 = *(float4*)&Qs[i0+3][dd];
            a0 = fmaf(v0.x,kv.x, fmaf(v0.y,kv.y, fmaf(v0.z,kv.z, fmaf(v0.w,kv.w, a0))));
            a1 = fmaf(v1.x,kv.x, fmaf(v1.y,kv.y, fmaf(v1.z,kv.z, fmaf(v1.w,kv.w, a1))));
            a2 = fmaf(v2.x,kv.x, fmaf(v2.y,kv.y, fmaf(v2.z,kv.z, fmaf(v2.w,kv.w, a2))));
            a3 = fmaf(v3.x,kv.x, fmaf(v3.y,kv.y, fmaf(v3.z,kv.z, fmaf(v3.w,kv.w, a3))));
        }
        int key = kb + jj;
        bool inr = (key >= 0 && key < S);
        float padp = (inr && tokens[key] == PAD_IDX) ? -1e30f : 0.f;
        float av[4] = {a0, a1, a2, a3};
#pragma unroll
        for (int r = 0; r < 4; r++) {
            int rp = key - (q0 + i0 + r);
            float sc;
            if (!inr || rp < -WIN || rp > WIN) sc = -3.0e38f;
            else sc = av[r] + g_brel[h*257 + rp + WIN] + padp;
            Sc[i0+r][c0+jj] = sc;
        }
    }
    __syncthreads();

    {
        int warp = tid >> 5, lane = tid & 31;
#pragma unroll
        for (int rr = 0; rr < 2; rr++) {
            int i = warp*2 + rr;
            float m = -3.4e38f;
            for (int j = lane; j < KWP; j += 32) m = fmaxf(m, Sc[i][j]);
#pragma unroll
            for (int off = 16; off; off >>= 1) m = fmaxf(m, __shfl_xor_sync(0xffffffffu, m, off));
            float ssum = 0.f;
            for (int j = lane; j < KWP; j += 32) {
                float e = expf(Sc[i][j] - m);
                Sc[i][j] = e; ssum += e;
            }
#pragma unroll
            for (int off = 16; off; off >>= 1) ssum += __shfl_xor_sync(0xffffffffu, ssum, off);
            float inv = 1.f / ssum;
            for (int j = lane; j < KWP; j += 32) Sc[i][j] *= inv;
        }
    }
    __syncthreads();

    int dd = tid & 63;
    float o0=0.f, o1=0.f, o2=0.f, o3=0.f;
    for (int c0 = 0; c0 < KWP; c0 += 64) {
        int kb = kstart + c0;
        if (kb >= S || kb + 63 < 0) continue;
        __syncthreads();
        {
            int r0 = (tid >> 4) << 2, d0 = (tid & 15) << 2;
#pragma unroll
            for (int u = 0; u < 4; u++) {
                int key = kb + r0 + u;
                float4 v = (key >= 0 && key < S) ? *(const float4*)(g_v + (size_t)key*D + h*HD + d0)
                                                 : make_float4(0.f,0.f,0.f,0.f);
                KV[d0+0][r0+u] = v.x; KV[d0+1][r0+u] = v.y;
                KV[d0+2][r0+u] = v.z; KV[d0+3][r0+u] = v.w;
            }
        }
        __syncthreads();
#pragma unroll
        for (int j = 0; j < 64; j += 4) {
            float4 vv = *(float4*)&KV[dd][j];
            float4 s0 = *(float4*)&Sc[i0+0][c0+j];
            float4 s1 = *(float4*)&Sc[i0+1][c0+j];
            float4 s2 = *(float4*)&Sc[i0+2][c0+j];
            float4 s3 = *(float4*)&Sc[i0+3][c0+j];
            o0 = fmaf(s0.x,vv.x, fmaf(s0.y,vv.y, fmaf(s0.z,vv.z, fmaf(s0.w,vv.w, o0))));
            o1 = fmaf(s1.x,vv.x, fmaf(s1.y,vv.y, fmaf(s1.z,vv.z, fmaf(s1.w,vv.w, o1))));
            o2 = fmaf(s2.x,vv.x, fmaf(s2.y,vv.y, fmaf(s2.z,vv.z, fmaf(s2.w,vv.w, o2))));
            o3 = fmaf(s3.x,vv.x, fmaf(s3.y,vv.y, fmaf(s3.z,vv.z, fmaf(s3.w,vv.w, o3))));
        }
    }
    g_o[(size_t)(q0+i0+0)*D + h*HD + dd] = o0;
    g_o[(size_t)(q0+i0+1)*D + h*HD + dd] = o1;
    g_o[(size_t)(q0+i0+2)*D + h*HD + dd] = o2;
    g_o[(size_t)(q0+i0+3)*D + h*HD + dd] = o3;
}

// ---------------- residual + LayerNorm (R12 verbatim) ----------------
template<bool TO_OUT>
__global__ __launch_bounds__(256) void ln_kernel(const float* __restrict__ sc,
    const float* __restrict__ bb, float* __restrict__ outp)
{
    float* dst = TO_OUT ? outp : g_x;
    __shared__ float red[256];
    __shared__ float sh_m, sh_r;
    int row = blockIdx.x, tid = threadIdx.x;
    size_t base = (size_t)row * D;
    float v0 = g_x[base + tid      ] + g_t[base + tid      ];
    float v1 = g_x[base + tid + 256] + g_t[base + tid + 256];
    float v2 = g_x[base + tid + 512] + g_t[base + tid + 512];
    red[tid] = v0 + v1 + v2;
    __syncthreads();
#pragma unroll
    for (int o2 = 128; o2; o2 >>= 1) { if (tid < o2) red[tid] += red[tid + o2]; __syncthreads(); }
    if (tid == 0) sh_m = red[0] * (1.f / 768.f);
    __syncthreads();
    float m = sh_m;
    float d0 = v0 - m, d1 = v1 - m, d2 = v2 - m;
    red[tid] = d0*d0 + d1*d1 + d2*d2;
    __syncthreads();
#pragma unroll
    for (int o2 = 128; o2; o2 >>= 1) { if (tid < o2) red[tid] += red[tid + o2]; __syncthreads(); }
    if (tid == 0) sh_r = rsqrtf(red[0] * (1.f / 768.f) + 1e-5f);
    __syncthreads();
    float r = sh_r;
    dst[base + tid      ] = d0 * r * sc[tid      ] + bb[tid      ];
    dst[base + tid + 256] = d1 * r * sc[tid + 256] + bb[tid + 256];
    dst[base + tid + 512] = d2 * r * sc[tid + 512] + bb[tid + 512];
}

// ---------------- driver ----------------
extern "C" void kernel_launch(void* const* d_in, const int* in_sizes, int n_in,
                              void* d_out, int out_size)
{
    const int*   tokens = (const int*)  d_in[0];
    const int*   segs   = (const int*)  d_in[1];
    const float* emb    = (const float*)d_in[2];
    const float* pemb   = (const float*)d_in[3];
    const float* semb   = (const float*)d_in[4];
    const float* relb   = (const float*)d_in[5];
    const float* Wq     = (const float*)d_in[6];
    const float* bq     = (const float*)d_in[7];
    const float* Wk     = (const float*)d_in[8];
    const float* bk     = (const float*)d_in[9];
    const float* Wv     = (const float*)d_in[10];
    const float* bv     = (const float*)d_in[11];
    const float* Wo     = (const float*)d_in[12];
    const float* bo     = (const float*)d_in[13];
    const float* ln1s   = (const float*)d_in[14];
    const float* ln1b   = (const float*)d_in[15];
    const float* W1     = (const float*)d_in[16];
    const float* b1     = (const float*)d_in[17];
    const float* W2     = (const float*)d_in[18];
    const float* b2     = (const float*)d_in[19];
    const float* ln2s   = (const float*)d_in[20];
    const float* ln2b   = (const float*)d_in[21];
    float* out = (float*)d_out;

    dim3 g768(D/64, S/128);        // (12, 16)
    dim3 gFF(FF/64, S/128);        // (48, 16)
    dim3 gqkv(D/64, S/128, 3);     // (12, 16, 3)
    dim3 gattn(S/BQ, H);           // (128, 12)
    dim3 ttb(32, 8);
    dim3 tgD(D/32, S/32);          // (24, 64)
    dim3 tgF(FF/32, S/32);         // (96, 64)

    pos_kernel<<<1, 256>>>(tokens);
    relbias_kernel<<<1, 288>>>(relb);
    embed_kernel<<<S, 192>>>(tokens, segs, emb, pemb, semb);

    for (int l = 0; l < L; l++) {
        size_t wdd = (size_t)l * D * D;
        transp_tpl<0><<<tgD, ttb>>>(S, D);
        gemm_qkv<<<gqkv, 128>>>(Wq + wdd, Wk + wdd, Wv + wdd,
                                bq + l*D, bk + l*D, bv + l*D);
        attn_kernel<<<gattn, 256>>>(tokens);
        transp_tpl<4><<<tgD, ttb>>>(S, D);
        gemm_tpl<4,5><<<g768, 128>>>(Wo + wdd, bo + l*D, D, D, 1.f, 0);
        ln_kernel<false><<<S, 256>>>(ln1s + l*D, ln1b + l*D, nullptr);
        transp_tpl<0><<<tgD, ttb>>>(S, D);
        gemm_tpl<0,6><<<gFF, 128>>>(W1 + (size_t)l*D*FF, b1 + (size_t)l*FF, FF, D, 1.f, 1);
        transp_tpl<6><<<tgF, ttb>>>(S, FF);
        gemm_tpl<6,5><<<g768, 128>>>(W2 + (size_t)l*FF*D, b2 + l*D, D, FF, 1.f, 0);
        if (l == L-1) ln_kernel<true ><<<S, 256>>>(ln2s + l*D, ln2b + l*D, out);
        else          ln_kernel<false><<<S, 256>>>(ln2s + l*D, ln2b + l*D, nullptr);
    }
}